// round 7
// baseline (speedup 1.0000x reference)
#include <cuda_runtime.h>

#define BB 4
#define LL 1024
#define DD 64
#define UU 32
#define NT 11          // u < NT : tanh.approx path ; u >= NT : ex2+Newton path
#define TI 8           // i-rows per CTA
#define JC 64          // k-chunk rows
#define EST 1040       // e-tile row stride (1040 % 32 == 16 -> disjoint bank halves)
#define KST 33         // k-chunk row stride (conflict-free)

#define L2E2 2.8853900817779268f   // 2*log2(e)

// Scratch: q/k projections, per-u scaled for the hybrid tanh paths.
__device__ float g_q[BB * LL * UU];
__device__ float g_k[BB * LL * UU];
__device__ float g_wah[UU + 1];    // [u<NT]: wa_u ; [u>=NT]: -2*wa_u ; [UU]: sum_{u>=NT} wa_u

// ---------------------------------------------------------------------------
// Kernel 1: per-row projection with per-u hybrid scaling.
//   u <  NT : q = x@Wt + bh            (tanh path, raw argument)
//   u >= NT : q = (x@Wt + bh)*2log2e   (Newton path, pre-scaled for ex2)
// ---------------------------------------------------------------------------
__global__ void qk_proj_kernel(const float* __restrict__ x,
                               const float* __restrict__ Wt,
                               const float* __restrict__ Wx,
                               const float* __restrict__ bh,
                               const float* __restrict__ Wa) {
    __shared__ float sx[DD];
    const int row = blockIdx.x;
    const int tid = threadIdx.x;
    if (tid < DD) sx[tid] = x[row * DD + tid];
    __syncthreads();

    const int u = tid & 31;
    const float* W = (tid < 32) ? Wt : Wx;
    float acc = 0.0f;
#pragma unroll
    for (int d = 0; d < DD; d++) acc = fmaf(sx[d], W[d * UU + u], acc);

    const float c = (u < NT) ? 1.0f : L2E2;
    if (tid < 32) g_q[row * UU + u] = (acc + bh[u]) * c;
    else          g_k[row * UU + u] = acc * c;

    // block 0 also prepares the hybrid weight table + bias
    if (blockIdx.x == 0 && tid < 32) {
        float w = Wa[tid];
        g_wah[tid] = (tid < NT) ? w : (-2.0f * w);
        if (tid == 0) {
            float s = 0.0f;
#pragma unroll
            for (int uu = NT; uu < UU; uu++) s += Wa[uu];
            g_wah[UU] = s;
        }
    }
}

// ---------------------------------------------------------------------------
__device__ __forceinline__ float tanhf_fast(float z) {
    float t;
    asm("tanh.approx.f32 %0, %1;" : "=f"(t) : "f"(z));
    return t;
}
__device__ __forceinline__ float ex2f(float z) {
    float t;
    asm("ex2.approx.f32 %0, %1;" : "=f"(t) : "f"(z));
    return t;
}

// ---------------------------------------------------------------------------
// Kernel 2: fused e / softmax / a@X.  grid = B * (L/TI) = 512 blocks, 256 thr.
// ---------------------------------------------------------------------------
__global__ __launch_bounds__(256, 4)
void attn_kernel(const float* __restrict__ x,
                 float* __restrict__ out) {
    extern __shared__ float smem[];
    float* et   = smem;                       // TI * EST
    float* kch  = et + TI * EST;              // JC * KST
    float* sq   = kch + JC * KST;             // TI * UU
    float* swah = sq + TI * UU;               // UU + 1
    float* rinv = swah + UU + 1;              // TI

    const int tid = threadIdx.x;
    const int b   = blockIdx.x / (LL / TI);
    const int i0  = (blockIdx.x % (LL / TI)) * TI;

    // q rows for this tile + weight table -> smem
    sq[tid] = g_q[(b * LL + i0 + (tid >> 5)) * UU + (tid & 31)];
    if (tid < UU + 1) swah[tid] = g_wah[tid];

    // ---------------- Phase A: e[i][j] (hybrid MUFU/FMA tanh) ----------------
    {
        const int i_loc = tid >> 5;   // warp id == i row
        const int jl    = tid & 31;

        const float* kb = &g_k[b * LL * UU];
        const float* qs = &sq[i_loc * UU];
        float* erow = &et[i_loc * EST];

        for (int jc = 0; jc < LL; jc += JC) {
            __syncthreads();
#pragma unroll
            for (int t = 0; t < (JC * UU) / 256; t++) {
                int idx = tid + t * 256;
                kch[(idx >> 5) * KST + (idx & 31)] = kb[(jc + (idx >> 5)) * UU + (idx & 31)];
            }
            __syncthreads();

            const float bias = swah[UU];
#pragma unroll
            for (int s = 0; s < JC / 32; s++) {
                const int j = jl + 32 * s;
                const float* krow = &kch[j * KST];
                float e0 = bias, e1 = 0.0f;
                // tanh.approx path (MUFU-heavy)
#pragma unroll
                for (int u = 0; u < NT; u++) {
                    float z = qs[u] + krow[u];
                    e0 = fmaf(swah[u], tanhf_fast(z), e0);
                }
                // ex2 + fast-reciprocal path (FMA-heavy)
#pragma unroll
                for (int u = NT; u < UU; u++) {
                    float w = qs[u] + krow[u];        // pre-scaled by 2log2e
                    float y = ex2f(w) + 1.0f;         // y in [1, ~3e7]
                    float r = __int_as_float(0x7EF311C3 - __float_as_int(y));
                    r = r * fmaf(-r, y, 2.0f);        // Newton 1
                    r = r * fmaf(-r, y, 2.0f);        // Newton 2  (rel err ~1e-5)
                    e1 = fmaf(swah[u], r, e1);        // swah = -2*wa ; +wa in bias
                }
                erow[jc + j] = e0 + e1;               // ba dropped: shift-invariant
            }
        }
        __syncthreads();
    }

    // ---------------- Phase B: softmax (one warp per row) ----------------
    {
        const int i    = tid >> 5;
        const int lane = tid & 31;
        const float L2E = 1.4426950408889634f;
        float* row = &et[i * EST];
        float m = -1e30f;
        for (int j = lane; j < LL; j += 32) m = fmaxf(m, row[j]);
#pragma unroll
        for (int o = 16; o; o >>= 1) m = fmaxf(m, __shfl_xor_sync(0xFFFFFFFFu, m, o));
        float s = 0.0f;
        for (int j = lane; j < LL; j += 32) {
            float p = ex2f((row[j] - m) * L2E);
            row[j] = p;
            s += p;
        }
#pragma unroll
        for (int o = 16; o; o >>= 1) s += __shfl_xor_sync(0xFFFFFFFFu, s, o);
        if (lane == 0) rinv[i] = 1.0f / (s + 1e-8f);
    }
    __syncthreads();

    // ---------------- Phase C: v = a @ X, j split across warps ----------------
    {
        const int lane = tid & 31;
        const int w    = tid >> 5;          // owns j in [w*128, w*128+128)
        const int j0   = w * (LL / 8);
        const float2* x2 = (const float2*)(x + (size_t)b * LL * DD);

        float accx[TI], accy[TI];
#pragma unroll
        for (int i = 0; i < TI; i++) { accx[i] = 0.0f; accy[i] = 0.0f; }

        for (int j = j0; j < j0 + LL / 8; j += 4) {
            float2 xv0 = x2[(j + 0) * 32 + lane];
            float2 xv1 = x2[(j + 1) * 32 + lane];
            float2 xv2 = x2[(j + 2) * 32 + lane];
            float2 xv3 = x2[(j + 3) * 32 + lane];
#pragma unroll
            for (int i = 0; i < TI; i++) {
                float4 p = *(const float4*)&et[i * EST + j];
                accx[i] = fmaf(p.x, xv0.x, accx[i]); accy[i] = fmaf(p.x, xv0.y, accy[i]);
                accx[i] = fmaf(p.y, xv1.x, accx[i]); accy[i] = fmaf(p.y, xv1.y, accy[i]);
                accx[i] = fmaf(p.z, xv2.x, accx[i]); accy[i] = fmaf(p.z, xv2.y, accy[i]);
                accx[i] = fmaf(p.w, xv3.x, accx[i]); accy[i] = fmaf(p.w, xv3.y, accy[i]);
            }
        }
        __syncthreads();   // all warps done reading et

        float* part = et;
#pragma unroll
        for (int i = 0; i < TI; i++) {
            *(float2*)&part[w * (TI * DD) + i * DD + 2 * lane] = make_float2(accx[i], accy[i]);
        }
        __syncthreads();

        const int ir = tid >> 5;
        float2 s = make_float2(0.0f, 0.0f);
#pragma unroll
        for (int ww = 0; ww < 8; ww++) {
            float2 pv = *(const float2*)&part[ww * (TI * DD) + ir * DD + 2 * lane];
            s.x += pv.x; s.y += pv.y;
        }
        const float r = rinv[ir];
        *(float2*)&out[((size_t)b * LL + i0 + ir) * DD + 2 * lane] =
            make_float2(s.x * r, s.y * r);
    }
}

// ---------------------------------------------------------------------------
extern "C" void kernel_launch(void* const* d_in, const int* in_sizes, int n_in,
                              void* d_out, int out_size) {
    const float* x   = (const float*)d_in[0];
    const float* Wt  = (const float*)d_in[1];
    const float* Wx  = (const float*)d_in[2];
    const float* Wa  = (const float*)d_in[3];
    const float* bh  = (const float*)d_in[4];
    // d_in[5] = ba : cancels under softmax -> unused
    // d_in[6] = attention_width : dead code in reference -> unused
    float* out = (float*)d_out;

    const int smem_bytes = (TI * EST + JC * KST + TI * UU + UU + 1 + TI) * (int)sizeof(float);
    cudaFuncSetAttribute(attn_kernel, cudaFuncAttributeMaxDynamicSharedMemorySize, smem_bytes);

    qk_proj_kernel<<<BB * LL, 64>>>(x, Wt, Wx, bh, Wa);
    attn_kernel<<<BB * (LL / TI), 256, smem_bytes>>>(x, out);
}

// round 8
// speedup vs baseline: 1.0011x; 1.0011x over previous
#include <cuda_runtime.h>

#define BB 4
#define LL 1024
#define DD 64
#define UU 32
#define NT 11          // u < NT : tanh.approx path ; u >= NT : ex2+Newton path
#define TI 8           // i-rows per CTA
#define JC 64          // k-chunk rows
#define EST 1040       // e-tile row stride (1040 % 32 == 16 -> disjoint bank halves)
#define KST 33         // k-chunk row stride (conflict-free)

#define L2E2 2.8853900817779268f   // 2*log2(e)

// Scratch: q/k projections, per-u scaled for the hybrid tanh paths.
__device__ float g_q[BB * LL * UU];
__device__ float g_k[BB * LL * UU];
__device__ float g_wah[UU + 1];    // [u<NT]: wa_u ; [u>=NT]: -2*wa_u ; [UU]: sum_{u>=NT} wa_u

// ---------------------------------------------------------------------------
// Kernel 1: per-row projection with per-u hybrid scaling.
//   u <  NT : q = x@Wt + bh            (tanh path, raw argument)
//   u >= NT : q = (x@Wt + bh)*2log2e   (Newton path, pre-scaled for ex2)
// ---------------------------------------------------------------------------
__global__ void qk_proj_kernel(const float* __restrict__ x,
                               const float* __restrict__ Wt,
                               const float* __restrict__ Wx,
                               const float* __restrict__ bh,
                               const float* __restrict__ Wa) {
    __shared__ float sx[DD];
    const int row = blockIdx.x;
    const int tid = threadIdx.x;
    if (tid < DD) sx[tid] = x[row * DD + tid];
    __syncthreads();

    const int u = tid & 31;
    const float* W = (tid < 32) ? Wt : Wx;
    float acc = 0.0f;
#pragma unroll
    for (int d = 0; d < DD; d++) acc = fmaf(sx[d], W[d * UU + u], acc);

    const float c = (u < NT) ? 1.0f : L2E2;
    if (tid < 32) g_q[row * UU + u] = (acc + bh[u]) * c;
    else          g_k[row * UU + u] = acc * c;

    // block 0 also prepares the hybrid weight table + bias
    if (blockIdx.x == 0 && tid < 32) {
        float w = Wa[tid];
        g_wah[tid] = (tid < NT) ? w : (-2.0f * w);
        if (tid == 0) {
            float s = 0.0f;
#pragma unroll
            for (int uu = NT; uu < UU; uu++) s += Wa[uu];
            g_wah[UU] = s;
        }
    }
}

// ---------------------------------------------------------------------------
__device__ __forceinline__ float tanhf_fast(float z) {
    float t;
    asm("tanh.approx.f32 %0, %1;" : "=f"(t) : "f"(z));
    return t;
}
__device__ __forceinline__ float ex2f(float z) {
    float t;
    asm("ex2.approx.f32 %0, %1;" : "=f"(t) : "f"(z));
    return t;
}

// ---------------------------------------------------------------------------
// Kernel 2: fused e / softmax / a@X.  grid = B * (L/TI) = 512 blocks, 256 thr.
// ---------------------------------------------------------------------------
__global__ __launch_bounds__(256, 4)
void attn_kernel(const float* __restrict__ x,
                 float* __restrict__ out) {
    extern __shared__ float smem[];
    float* et   = smem;                       // TI * EST
    float* kch  = et + TI * EST;              // JC * KST
    float* sq   = kch + JC * KST;             // TI * UU
    float* swah = sq + TI * UU;               // UU + 1
    float* rinv = swah + UU + 1;              // TI

    const int tid = threadIdx.x;
    const int b   = blockIdx.x / (LL / TI);
    const int i0  = (blockIdx.x % (LL / TI)) * TI;

    // q rows for this tile + weight table -> smem
    sq[tid] = g_q[(b * LL + i0 + (tid >> 5)) * UU + (tid & 31)];
    if (tid < UU + 1) swah[tid] = g_wah[tid];

    // ---------------- Phase A: e[i][j] (hybrid MUFU/FMA tanh) ----------------
    {
        const int i_loc = tid >> 5;   // warp id == i row
        const int jl    = tid & 31;

        const float* kb = &g_k[b * LL * UU];
        const float* qs = &sq[i_loc * UU];
        float* erow = &et[i_loc * EST];

        for (int jc = 0; jc < LL; jc += JC) {
            __syncthreads();
#pragma unroll
            for (int t = 0; t < (JC * UU) / 256; t++) {
                int idx = tid + t * 256;
                kch[(idx >> 5) * KST + (idx & 31)] = kb[(jc + (idx >> 5)) * UU + (idx & 31)];
            }
            __syncthreads();

            const float bias = swah[UU];
#pragma unroll
            for (int s = 0; s < JC / 32; s++) {
                const int j = jl + 32 * s;
                const float* krow = &kch[j * KST];
                float e0 = bias, e1 = 0.0f;
                // tanh.approx path (MUFU-heavy)
#pragma unroll
                for (int u = 0; u < NT; u++) {
                    float z = qs[u] + krow[u];
                    e0 = fmaf(swah[u], tanhf_fast(z), e0);
                }
                // ex2 + fast-reciprocal path (FMA-heavy)
#pragma unroll
                for (int u = NT; u < UU; u++) {
                    float w = qs[u] + krow[u];        // pre-scaled by 2log2e
                    float y = ex2f(w) + 1.0f;         // y in [1, ~3e7]
                    float r = __int_as_float(0x7EF311C3 - __float_as_int(y));
                    r = r * fmaf(-r, y, 2.0f);        // Newton 1
                    r = r * fmaf(-r, y, 2.0f);        // Newton 2  (rel err ~1e-5)
                    e1 = fmaf(swah[u], r, e1);        // swah = -2*wa ; +wa in bias
                }
                erow[jc + j] = e0 + e1;               // ba dropped: shift-invariant
            }
        }
        __syncthreads();
    }

    // ---------------- Phase B: softmax (one warp per row) ----------------
    {
        const int i    = tid >> 5;
        const int lane = tid & 31;
        const float L2E = 1.4426950408889634f;
        float* row = &et[i * EST];
        float m = -1e30f;
        for (int j = lane; j < LL; j += 32) m = fmaxf(m, row[j]);
#pragma unroll
        for (int o = 16; o; o >>= 1) m = fmaxf(m, __shfl_xor_sync(0xFFFFFFFFu, m, o));
        float s = 0.0f;
        for (int j = lane; j < LL; j += 32) {
            float p = ex2f((row[j] - m) * L2E);
            row[j] = p;
            s += p;
        }
#pragma unroll
        for (int o = 16; o; o >>= 1) s += __shfl_xor_sync(0xFFFFFFFFu, s, o);
        if (lane == 0) rinv[i] = 1.0f / (s + 1e-8f);
    }
    __syncthreads();

    // ---------------- Phase C: v = a @ X, j split across warps ----------------
    {
        const int lane = tid & 31;
        const int w    = tid >> 5;          // owns j in [w*128, w*128+128)
        const int j0   = w * (LL / 8);
        const float2* x2 = (const float2*)(x + (size_t)b * LL * DD);

        float accx[TI], accy[TI];
#pragma unroll
        for (int i = 0; i < TI; i++) { accx[i] = 0.0f; accy[i] = 0.0f; }

        for (int j = j0; j < j0 + LL / 8; j += 4) {
            float2 xv0 = x2[(j + 0) * 32 + lane];
            float2 xv1 = x2[(j + 1) * 32 + lane];
            float2 xv2 = x2[(j + 2) * 32 + lane];
            float2 xv3 = x2[(j + 3) * 32 + lane];
#pragma unroll
            for (int i = 0; i < TI; i++) {
                float4 p = *(const float4*)&et[i * EST + j];
                accx[i] = fmaf(p.x, xv0.x, accx[i]); accy[i] = fmaf(p.x, xv0.y, accy[i]);
                accx[i] = fmaf(p.y, xv1.x, accx[i]); accy[i] = fmaf(p.y, xv1.y, accy[i]);
                accx[i] = fmaf(p.z, xv2.x, accx[i]); accy[i] = fmaf(p.z, xv2.y, accy[i]);
                accx[i] = fmaf(p.w, xv3.x, accx[i]); accy[i] = fmaf(p.w, xv3.y, accy[i]);
            }
        }
        __syncthreads();   // all warps done reading et

        float* part = et;
#pragma unroll
        for (int i = 0; i < TI; i++) {
            *(float2*)&part[w * (TI * DD) + i * DD + 2 * lane] = make_float2(accx[i], accy[i]);
        }
        __syncthreads();

        const int ir = tid >> 5;
        float2 s = make_float2(0.0f, 0.0f);
#pragma unroll
        for (int ww = 0; ww < 8; ww++) {
            float2 pv = *(const float2*)&part[ww * (TI * DD) + ir * DD + 2 * lane];
            s.x += pv.x; s.y += pv.y;
        }
        const float r = rinv[ir];
        *(float2*)&out[((size_t)b * LL + i0 + ir) * DD + 2 * lane] =
            make_float2(s.x * r, s.y * r);
    }
}

// ---------------------------------------------------------------------------
extern "C" void kernel_launch(void* const* d_in, const int* in_sizes, int n_in,
                              void* d_out, int out_size) {
    const float* x   = (const float*)d_in[0];
    const float* Wt  = (const float*)d_in[1];
    const float* Wx  = (const float*)d_in[2];
    const float* Wa  = (const float*)d_in[3];
    const float* bh  = (const float*)d_in[4];
    // d_in[5] = ba : cancels under softmax -> unused
    // d_in[6] = attention_width : dead code in reference -> unused
    float* out = (float*)d_out;

    const int smem_bytes = (TI * EST + JC * KST + TI * UU + UU + 1 + TI) * (int)sizeof(float);
    cudaFuncSetAttribute(attn_kernel, cudaFuncAttributeMaxDynamicSharedMemorySize, smem_bytes);

    qk_proj_kernel<<<BB * LL, 64>>>(x, Wt, Wx, bh, Wa);
    attn_kernel<<<BB * (LL / TI), 256, smem_bytes>>>(x, out);
}

// round 9
// speedup vs baseline: 1.0037x; 1.0026x over previous
#include <cuda_runtime.h>

#define BB 4
#define LL 1024
#define DD 64
#define UU 32
#define NT 11          // u < NT : tanh.approx path ; u >= NT : ex2+Newton path
#define TI 8           // i-rows per CTA
#define JC 64          // k-chunk rows
#define EST 1040       // e-tile row stride (1040 % 32 == 16 -> disjoint bank halves)
#define KST 33         // k-chunk row stride (conflict-free)

#define L2E2 2.8853900817779268f   // 2*log2(e)

// Scratch: q/k projections, per-u scaled for the hybrid tanh paths.
__device__ float g_q[BB * LL * UU];
__device__ float g_k[BB * LL * UU];
__device__ float g_wah[UU + 1];    // [u<NT]: wa_u ; [u>=NT]: -2*wa_u ; [UU]: sum_{u>=NT} wa_u

// ---------------------------------------------------------------------------
// Kernel 1: per-row projection with per-u hybrid scaling.
//   u <  NT : q = x@Wt + bh            (tanh path, raw argument)
//   u >= NT : q = (x@Wt + bh)*2log2e   (Newton path, pre-scaled for ex2)
// ---------------------------------------------------------------------------
__global__ void qk_proj_kernel(const float* __restrict__ x,
                               const float* __restrict__ Wt,
                               const float* __restrict__ Wx,
                               const float* __restrict__ bh,
                               const float* __restrict__ Wa) {
    __shared__ float sx[DD];
    const int row = blockIdx.x;
    const int tid = threadIdx.x;
    if (tid < DD) sx[tid] = x[row * DD + tid];
    __syncthreads();

    const int u = tid & 31;
    const float* W = (tid < 32) ? Wt : Wx;
    float acc = 0.0f;
#pragma unroll
    for (int d = 0; d < DD; d++) acc = fmaf(sx[d], W[d * UU + u], acc);

    const float c = (u < NT) ? 1.0f : L2E2;
    if (tid < 32) g_q[row * UU + u] = (acc + bh[u]) * c;
    else          g_k[row * UU + u] = acc * c;

    // block 0 also prepares the hybrid weight table + bias
    if (blockIdx.x == 0 && tid < 32) {
        float w = Wa[tid];
        g_wah[tid] = (tid < NT) ? w : (-2.0f * w);
        if (tid == 0) {
            float s = 0.0f;
#pragma unroll
            for (int uu = NT; uu < UU; uu++) s += Wa[uu];
            g_wah[UU] = s;
        }
    }
}

// ---------------------------------------------------------------------------
__device__ __forceinline__ float tanhf_fast(float z) {
    float t;
    asm("tanh.approx.f32 %0, %1;" : "=f"(t) : "f"(z));
    return t;
}
__device__ __forceinline__ float ex2f(float z) {
    float t;
    asm("ex2.approx.f32 %0, %1;" : "=f"(t) : "f"(z));
    return t;
}

// ---------------------------------------------------------------------------
// Kernel 2: fused e / softmax / a@X.  grid = B * (L/TI) = 512 blocks, 256 thr.
// ---------------------------------------------------------------------------
__global__ __launch_bounds__(256, 4)
void attn_kernel(const float* __restrict__ x,
                 float* __restrict__ out) {
    extern __shared__ float smem[];
    float* et   = smem;                       // TI * EST
    float* kch  = et + TI * EST;              // JC * KST
    float* sq   = kch + JC * KST;             // TI * UU
    float* swah = sq + TI * UU;               // UU + 1
    float* rinv = swah + UU + 1;              // TI

    const int tid = threadIdx.x;
    const int b   = blockIdx.x / (LL / TI);
    const int i0  = (blockIdx.x % (LL / TI)) * TI;

    // q rows for this tile + weight table -> smem
    sq[tid] = g_q[(b * LL + i0 + (tid >> 5)) * UU + (tid & 31)];
    if (tid < UU + 1) swah[tid] = g_wah[tid];

    // ---------------- Phase A: e[i][j] (hybrid MUFU/FMA tanh) ----------------
    {
        const int i_loc = tid >> 5;   // warp id == i row
        const int jl    = tid & 31;

        const float* kb = &g_k[b * LL * UU];
        const float* qs = &sq[i_loc * UU];
        float* erow = &et[i_loc * EST];

        for (int jc = 0; jc < LL; jc += JC) {
            __syncthreads();
#pragma unroll
            for (int t = 0; t < (JC * UU) / 256; t++) {
                int idx = tid + t * 256;
                kch[(idx >> 5) * KST + (idx & 31)] = kb[(jc + (idx >> 5)) * UU + (idx & 31)];
            }
            __syncthreads();

            const float bias = swah[UU];
#pragma unroll
            for (int s = 0; s < JC / 32; s++) {
                const int j = jl + 32 * s;
                const float* krow = &kch[j * KST];
                float e0 = bias, e1 = 0.0f;
                // tanh.approx path (MUFU-heavy)
#pragma unroll
                for (int u = 0; u < NT; u++) {
                    float z = qs[u] + krow[u];
                    e0 = fmaf(swah[u], tanhf_fast(z), e0);
                }
                // ex2 + fast-reciprocal path (FMA-heavy)
#pragma unroll
                for (int u = NT; u < UU; u++) {
                    float w = qs[u] + krow[u];        // pre-scaled by 2log2e
                    float y = ex2f(w) + 1.0f;         // y in [1, ~3e7]
                    float r = __int_as_float(0x7EF311C3 - __float_as_int(y));
                    r = r * fmaf(-r, y, 2.0f);        // Newton 1
                    r = r * fmaf(-r, y, 2.0f);        // Newton 2  (rel err ~1e-5)
                    e1 = fmaf(swah[u], r, e1);        // swah = -2*wa ; +wa in bias
                }
                erow[jc + j] = e0 + e1;               // ba dropped: shift-invariant
            }
        }
        __syncthreads();
    }

    // ---------------- Phase B: softmax (one warp per row) ----------------
    {
        const int i    = tid >> 5;
        const int lane = tid & 31;
        const float L2E = 1.4426950408889634f;
        float* row = &et[i * EST];
        float m = -1e30f;
        for (int j = lane; j < LL; j += 32) m = fmaxf(m, row[j]);
#pragma unroll
        for (int o = 16; o; o >>= 1) m = fmaxf(m, __shfl_xor_sync(0xFFFFFFFFu, m, o));
        float s = 0.0f;
        for (int j = lane; j < LL; j += 32) {
            float p = ex2f((row[j] - m) * L2E);
            row[j] = p;
            s += p;
        }
#pragma unroll
        for (int o = 16; o; o >>= 1) s += __shfl_xor_sync(0xFFFFFFFFu, s, o);
        if (lane == 0) rinv[i] = 1.0f / (s + 1e-8f);
    }
    __syncthreads();

    // ---------------- Phase C: v = a @ X, j split across warps ----------------
    {
        const int lane = tid & 31;
        const int w    = tid >> 5;          // owns j in [w*128, w*128+128)
        const int j0   = w * (LL / 8);
        const float2* x2 = (const float2*)(x + (size_t)b * LL * DD);

        float accx[TI], accy[TI];
#pragma unroll
        for (int i = 0; i < TI; i++) { accx[i] = 0.0f; accy[i] = 0.0f; }

        for (int j = j0; j < j0 + LL / 8; j += 4) {
            float2 xv0 = x2[(j + 0) * 32 + lane];
            float2 xv1 = x2[(j + 1) * 32 + lane];
            float2 xv2 = x2[(j + 2) * 32 + lane];
            float2 xv3 = x2[(j + 3) * 32 + lane];
#pragma unroll
            for (int i = 0; i < TI; i++) {
                float4 p = *(const float4*)&et[i * EST + j];
                accx[i] = fmaf(p.x, xv0.x, accx[i]); accy[i] = fmaf(p.x, xv0.y, accy[i]);
                accx[i] = fmaf(p.y, xv1.x, accx[i]); accy[i] = fmaf(p.y, xv1.y, accy[i]);
                accx[i] = fmaf(p.z, xv2.x, accx[i]); accy[i] = fmaf(p.z, xv2.y, accy[i]);
                accx[i] = fmaf(p.w, xv3.x, accx[i]); accy[i] = fmaf(p.w, xv3.y, accy[i]);
            }
        }
        __syncthreads();   // all warps done reading et

        float* part = et;
#pragma unroll
        for (int i = 0; i < TI; i++) {
            *(float2*)&part[w * (TI * DD) + i * DD + 2 * lane] = make_float2(accx[i], accy[i]);
        }
        __syncthreads();

        const int ir = tid >> 5;
        float2 s = make_float2(0.0f, 0.0f);
#pragma unroll
        for (int ww = 0; ww < 8; ww++) {
            float2 pv = *(const float2*)&part[ww * (TI * DD) + ir * DD + 2 * lane];
            s.x += pv.x; s.y += pv.y;
        }
        const float r = rinv[ir];
        *(float2*)&out[((size_t)b * LL + i0 + ir) * DD + 2 * lane] =
            make_float2(s.x * r, s.y * r);
    }
}

// ---------------------------------------------------------------------------
extern "C" void kernel_launch(void* const* d_in, const int* in_sizes, int n_in,
                              void* d_out, int out_size) {
    const float* x   = (const float*)d_in[0];
    const float* Wt  = (const float*)d_in[1];
    const float* Wx  = (const float*)d_in[2];
    const float* Wa  = (const float*)d_in[3];
    const float* bh  = (const float*)d_in[4];
    // d_in[5] = ba : cancels under softmax -> unused
    // d_in[6] = attention_width : dead code in reference -> unused
    float* out = (float*)d_out;

    const int smem_bytes = (TI * EST + JC * KST + TI * UU + UU + 1 + TI) * (int)sizeof(float);
    cudaFuncSetAttribute(attn_kernel, cudaFuncAttributeMaxDynamicSharedMemorySize, smem_bytes);

    qk_proj_kernel<<<BB * LL, 64>>>(x, Wt, Wx, bh, Wa);
    attn_kernel<<<BB * (LL / TI), 256, smem_bytes>>>(x, out);
}

// round 10
// speedup vs baseline: 1.3096x; 1.3047x over previous
#include <cuda_runtime.h>
#include <cuda_fp16.h>
#include <cstdint>

#define BB 4
#define LL 1024
#define DD 64
#define UU 32
#define UH 16          // half2 groups per row (UU/2)
#define TI 8           // i-rows per CTA
#define JC 64          // k-chunk rows
#define EST 1040       // e-tile row stride in floats (disjoint bank halves)
#define KST2 20        // k-chunk row stride in half2 (80B: LDS.128 conflict-free)

// q = x@Wt + bh, k = x@Wx, packed to half2 pairs along u.
__device__ __half2 g_q2[BB * LL * UH];
__device__ __half2 g_k2[BB * LL * UH];

// ---------------------------------------------------------------------------
// Kernel 1: projection + half2 packing.
// ---------------------------------------------------------------------------
__global__ void qk_proj_kernel(const float* __restrict__ x,
                               const float* __restrict__ Wt,
                               const float* __restrict__ Wx,
                               const float* __restrict__ bh) {
    __shared__ float sx[DD];
    __shared__ float sres[64];
    const int row = blockIdx.x;
    const int tid = threadIdx.x;
    if (tid < DD) sx[tid] = x[row * DD + tid];
    __syncthreads();

    const int u = tid & 31;
    const float* W = (tid < 32) ? Wt : Wx;
    float acc = 0.0f;
#pragma unroll
    for (int d = 0; d < DD; d++) acc = fmaf(sx[d], W[d * UU + u], acc);
    if (tid < 32) acc += bh[u];
    sres[tid] = acc;
    __syncthreads();

    if (tid < UH) {
        g_q2[row * UH + tid] = __floats2half2_rn(sres[2 * tid], sres[2 * tid + 1]);
    } else if (tid < 32) {
        const int u2 = tid - UH;
        g_k2[row * UH + u2] = __floats2half2_rn(sres[32 + 2 * u2], sres[33 + 2 * u2]);
    }
}

// ---------------------------------------------------------------------------
__device__ __forceinline__ uint32_t hadd2u(uint32_t a, uint32_t b) {
    uint32_t c;
    asm("add.f16x2 %0, %1, %2;" : "=r"(c) : "r"(a), "r"(b));
    return c;
}
__device__ __forceinline__ float2 tanh2f(uint32_t z) {
    uint32_t t;
    asm("tanh.approx.f16x2 %0, %1;" : "=r"(t) : "r"(z));
    __half2 h = *reinterpret_cast<__half2*>(&t);
    return __half22float2(h);
}
__device__ __forceinline__ float ex2f(float z) {
    float t;
    asm("ex2.approx.f32 %0, %1;" : "=f"(t) : "f"(z));
    return t;
}

// ---------------------------------------------------------------------------
// Kernel 2: fused e / softmax / a@X.  grid = B*(L/TI) = 512 blocks, 256 thr.
// smem(words): et[TI*EST]=8320 | kch[JC*KST2]=1280 | sq[TI*UH]=128 | rinv[TI]
// ---------------------------------------------------------------------------
__global__ __launch_bounds__(256, 4)
void attn_kernel(const float* __restrict__ x,
                 const float* __restrict__ Wa,
                 float* __restrict__ out) {
    extern __shared__ float smem[];
    float*    et   = smem;                              // 8320 floats
    uint32_t* kch  = (uint32_t*)(smem + TI * EST);      // 1280 words (half2)
    uint32_t* sq   = kch + JC * KST2;                   // 128 words (half2)
    float*    rinv = (float*)(sq + TI * UH);            // TI

    const int tid = threadIdx.x;
    const int b   = blockIdx.x / (LL / TI);
    const int i0  = (blockIdx.x % (LL / TI)) * TI;

    // q rows for this tile -> smem (packed half2)
    if (tid < TI * UH)
        sq[tid] = ((const uint32_t*)g_q2)[(b * LL + i0 + (tid >> 4)) * UH + (tid & 15)];

    // ---------------- Phase A: e[i][j] via tanh.approx.f16x2 ----------------
    {
        const int i_loc = tid >> 5;   // warp id == i row
        const int jl    = tid & 31;

        float wa[UU];
#pragma unroll
        for (int u = 0; u < UU; u++) wa[u] = Wa[u];

        const uint32_t* kb = (const uint32_t*)g_k2 + (size_t)b * LL * UH;
        float* erow = &et[i_loc * EST];
        const uint4* qr4 = (const uint4*)(sq + i_loc * UH);

        for (int jc = 0; jc < LL; jc += JC) {
            __syncthreads();
            // cooperative load: 64 rows x 16 half2, coalesced
#pragma unroll
            for (int t = 0; t < (JC * UH) / 256; t++) {
                int idx = tid + t * 256;
                kch[(idx >> 4) * KST2 + (idx & 15)] = kb[(jc + (idx >> 4)) * UH + (idx & 15)];
            }
            __syncthreads();

#pragma unroll
            for (int s = 0; s < JC / 32; s++) {
                const int j = jl + 32 * s;
                const uint4* kr4 = (const uint4*)(kch + j * KST2);
                float e0 = 0.0f, e1 = 0.0f;
#pragma unroll
                for (int G = 0; G < 4; G++) {
                    uint4 kv = kr4[G];
                    uint4 qv = qr4[G];     // warp-broadcast LDS.128
                    float2 t0 = tanh2f(hadd2u(qv.x, kv.x));
                    e0 = fmaf(wa[8 * G + 0], t0.x, e0);
                    e1 = fmaf(wa[8 * G + 1], t0.y, e1);
                    float2 t1 = tanh2f(hadd2u(qv.y, kv.y));
                    e0 = fmaf(wa[8 * G + 2], t1.x, e0);
                    e1 = fmaf(wa[8 * G + 3], t1.y, e1);
                    float2 t2 = tanh2f(hadd2u(qv.z, kv.z));
                    e0 = fmaf(wa[8 * G + 4], t2.x, e0);
                    e1 = fmaf(wa[8 * G + 5], t2.y, e1);
                    float2 t3 = tanh2f(hadd2u(qv.w, kv.w));
                    e0 = fmaf(wa[8 * G + 6], t3.x, e0);
                    e1 = fmaf(wa[8 * G + 7], t3.y, e1);
                }
                erow[jc + j] = e0 + e1;   // ba dropped: shift-invariant
            }
        }
        __syncthreads();
    }

    // ---------------- Phase B: softmax (one warp per row) ----------------
    {
        const int i    = tid >> 5;
        const int lane = tid & 31;
        const float L2E = 1.4426950408889634f;
        float* row = &et[i * EST];
        float m = -1e30f;
        for (int j = lane; j < LL; j += 32) m = fmaxf(m, row[j]);
#pragma unroll
        for (int o = 16; o; o >>= 1) m = fmaxf(m, __shfl_xor_sync(0xFFFFFFFFu, m, o));
        float s = 0.0f;
        for (int j = lane; j < LL; j += 32) {
            float p = ex2f((row[j] - m) * L2E);
            row[j] = p;
            s += p;
        }
#pragma unroll
        for (int o = 16; o; o >>= 1) s += __shfl_xor_sync(0xFFFFFFFFu, s, o);
        if (lane == 0) rinv[i] = 1.0f / (s + 1e-8f);
    }
    __syncthreads();

    // ---------------- Phase C: v = a @ X, j split across warps ----------------
    {
        const int lane = tid & 31;
        const int w    = tid >> 5;          // owns j in [w*128, w*128+128)
        const int j0   = w * (LL / 8);
        const float2* x2 = (const float2*)(x + (size_t)b * LL * DD);

        float accx[TI], accy[TI];
#pragma unroll
        for (int i = 0; i < TI; i++) { accx[i] = 0.0f; accy[i] = 0.0f; }

        for (int j = j0; j < j0 + LL / 8; j += 4) {
            float2 xv0 = x2[(j + 0) * 32 + lane];
            float2 xv1 = x2[(j + 1) * 32 + lane];
            float2 xv2 = x2[(j + 2) * 32 + lane];
            float2 xv3 = x2[(j + 3) * 32 + lane];
#pragma unroll
            for (int i = 0; i < TI; i++) {
                float4 p = *(const float4*)&et[i * EST + j];
                accx[i] = fmaf(p.x, xv0.x, accx[i]); accy[i] = fmaf(p.x, xv0.y, accy[i]);
                accx[i] = fmaf(p.y, xv1.x, accx[i]); accy[i] = fmaf(p.y, xv1.y, accy[i]);
                accx[i] = fmaf(p.z, xv2.x, accx[i]); accy[i] = fmaf(p.z, xv2.y, accy[i]);
                accx[i] = fmaf(p.w, xv3.x, accx[i]); accy[i] = fmaf(p.w, xv3.y, accy[i]);
            }
        }
        __syncthreads();   // all warps done reading et

        float* part = et;
#pragma unroll
        for (int i = 0; i < TI; i++) {
            *(float2*)&part[w * (TI * DD) + i * DD + 2 * lane] = make_float2(accx[i], accy[i]);
        }
        __syncthreads();

        const int ir = tid >> 5;
        float2 s = make_float2(0.0f, 0.0f);
#pragma unroll
        for (int ww = 0; ww < 8; ww++) {
            float2 pv = *(const float2*)&part[ww * (TI * DD) + ir * DD + 2 * lane];
            s.x += pv.x; s.y += pv.y;
        }
        const float r = rinv[ir];
        *(float2*)&out[((size_t)b * LL + i0 + ir) * DD + 2 * lane] =
            make_float2(s.x * r, s.y * r);
    }
}

// ---------------------------------------------------------------------------
extern "C" void kernel_launch(void* const* d_in, const int* in_sizes, int n_in,
                              void* d_out, int out_size) {
    const float* x   = (const float*)d_in[0];
    const float* Wt  = (const float*)d_in[1];
    const float* Wx  = (const float*)d_in[2];
    const float* Wa  = (const float*)d_in[3];
    const float* bh  = (const float*)d_in[4];
    // d_in[5] = ba : cancels under softmax -> unused
    // d_in[6] = attention_width : dead code in reference -> unused
    float* out = (float*)d_out;

    const int smem_bytes = (TI * EST + JC * KST2 + TI * UH + TI) * (int)sizeof(float);
    cudaFuncSetAttribute(attn_kernel, cudaFuncAttributeMaxDynamicSharedMemorySize, smem_bytes);

    qk_proj_kernel<<<BB * LL, 64>>>(x, Wt, Wx, bh);
    attn_kernel<<<BB * (LL / TI), 256, smem_bytes>>>(x, Wa, out);
}

// round 11
// speedup vs baseline: 1.3102x; 1.0005x over previous
#include <cuda_runtime.h>
#include <cuda_fp16.h>
#include <cstdint>

#define BB 4
#define LL 1024
#define DD 64
#define UU 32
#define UH 16          // half2 groups per row (UU/2)
#define TI 8           // i-rows per CTA
#define JC 64          // k-chunk rows
#define EST 1040       // e-tile row stride in floats (disjoint bank halves)
#define KST2 20        // k-chunk row stride in half2 (80B: LDS.128 conflict-free)

// q = x@Wt + bh, k = x@Wx, packed to half2 pairs along u.
__device__ __half2 g_q2[BB * LL * UH];
__device__ __half2 g_k2[BB * LL * UH];

// ---------------------------------------------------------------------------
// Kernel 1: projection + half2 packing.
// ---------------------------------------------------------------------------
__global__ void qk_proj_kernel(const float* __restrict__ x,
                               const float* __restrict__ Wt,
                               const float* __restrict__ Wx,
                               const float* __restrict__ bh) {
    __shared__ float sx[DD];
    __shared__ float sres[64];
    const int row = blockIdx.x;
    const int tid = threadIdx.x;
    if (tid < DD) sx[tid] = x[row * DD + tid];
    __syncthreads();

    const int u = tid & 31;
    const float* W = (tid < 32) ? Wt : Wx;
    float acc = 0.0f;
#pragma unroll
    for (int d = 0; d < DD; d++) acc = fmaf(sx[d], W[d * UU + u], acc);
    if (tid < 32) acc += bh[u];
    sres[tid] = acc;
    __syncthreads();

    if (tid < UH) {
        g_q2[row * UH + tid] = __floats2half2_rn(sres[2 * tid], sres[2 * tid + 1]);
    } else if (tid < 32) {
        const int u2 = tid - UH;
        g_k2[row * UH + u2] = __floats2half2_rn(sres[32 + 2 * u2], sres[33 + 2 * u2]);
    }
}

// ---------------------------------------------------------------------------
__device__ __forceinline__ uint32_t hadd2u(uint32_t a, uint32_t b) {
    uint32_t c;
    asm("add.f16x2 %0, %1, %2;" : "=r"(c) : "r"(a), "r"(b));
    return c;
}
__device__ __forceinline__ float2 tanh2f(uint32_t z) {
    uint32_t t;
    asm("tanh.approx.f16x2 %0, %1;" : "=r"(t) : "r"(z));
    __half2 h = *reinterpret_cast<__half2*>(&t);
    return __half22float2(h);
}
__device__ __forceinline__ float ex2f(float z) {
    float t;
    asm("ex2.approx.f32 %0, %1;" : "=f"(t) : "f"(z));
    return t;
}

// ---------------------------------------------------------------------------
// Kernel 2: fused e / softmax / a@X.  grid = B*(L/TI) = 512 blocks, 256 thr.
// smem(words): et[TI*EST]=8320 | kch[JC*KST2]=1280 | sq[TI*UH]=128 | rinv[TI]
// ---------------------------------------------------------------------------
__global__ __launch_bounds__(256, 4)
void attn_kernel(const float* __restrict__ x,
                 const float* __restrict__ Wa,
                 float* __restrict__ out) {
    extern __shared__ float smem[];
    float*    et   = smem;                              // 8320 floats
    uint32_t* kch  = (uint32_t*)(smem + TI * EST);      // 1280 words (half2)
    uint32_t* sq   = kch + JC * KST2;                   // 128 words (half2)
    float*    rinv = (float*)(sq + TI * UH);            // TI

    const int tid = threadIdx.x;
    const int b   = blockIdx.x / (LL / TI);
    const int i0  = (blockIdx.x % (LL / TI)) * TI;

    // q rows for this tile -> smem (packed half2)
    if (tid < TI * UH)
        sq[tid] = ((const uint32_t*)g_q2)[(b * LL + i0 + (tid >> 4)) * UH + (tid & 15)];

    // ---------------- Phase A: e[i][j] via tanh.approx.f16x2 ----------------
    {
        const int i_loc = tid >> 5;   // warp id == i row
        const int jl    = tid & 31;

        float wa[UU];
#pragma unroll
        for (int u = 0; u < UU; u++) wa[u] = Wa[u];

        const uint32_t* kb = (const uint32_t*)g_k2 + (size_t)b * LL * UH;
        float* erow = &et[i_loc * EST];
        const uint4* qr4 = (const uint4*)(sq + i_loc * UH);

        for (int jc = 0; jc < LL; jc += JC) {
            __syncthreads();
            // cooperative load: 64 rows x 16 half2, coalesced
#pragma unroll
            for (int t = 0; t < (JC * UH) / 256; t++) {
                int idx = tid + t * 256;
                kch[(idx >> 4) * KST2 + (idx & 15)] = kb[(jc + (idx >> 4)) * UH + (idx & 15)];
            }
            __syncthreads();

#pragma unroll
            for (int s = 0; s < JC / 32; s++) {
                const int j = jl + 32 * s;
                const uint4* kr4 = (const uint4*)(kch + j * KST2);
                float e0 = 0.0f, e1 = 0.0f;
#pragma unroll
                for (int G = 0; G < 4; G++) {
                    uint4 kv = kr4[G];
                    uint4 qv = qr4[G];     // warp-broadcast LDS.128
                    float2 t0 = tanh2f(hadd2u(qv.x, kv.x));
                    e0 = fmaf(wa[8 * G + 0], t0.x, e0);
                    e1 = fmaf(wa[8 * G + 1], t0.y, e1);
                    float2 t1 = tanh2f(hadd2u(qv.y, kv.y));
                    e0 = fmaf(wa[8 * G + 2], t1.x, e0);
                    e1 = fmaf(wa[8 * G + 3], t1.y, e1);
                    float2 t2 = tanh2f(hadd2u(qv.z, kv.z));
                    e0 = fmaf(wa[8 * G + 4], t2.x, e0);
                    e1 = fmaf(wa[8 * G + 5], t2.y, e1);
                    float2 t3 = tanh2f(hadd2u(qv.w, kv.w));
                    e0 = fmaf(wa[8 * G + 6], t3.x, e0);
                    e1 = fmaf(wa[8 * G + 7], t3.y, e1);
                }
                erow[jc + j] = e0 + e1;   // ba dropped: shift-invariant
            }
        }
        __syncthreads();
    }

    // ---------------- Phase B: softmax (one warp per row) ----------------
    {
        const int i    = tid >> 5;
        const int lane = tid & 31;
        const float L2E = 1.4426950408889634f;
        float* row = &et[i * EST];
        float m = -1e30f;
        for (int j = lane; j < LL; j += 32) m = fmaxf(m, row[j]);
#pragma unroll
        for (int o = 16; o; o >>= 1) m = fmaxf(m, __shfl_xor_sync(0xFFFFFFFFu, m, o));
        float s = 0.0f;
        for (int j = lane; j < LL; j += 32) {
            float p = ex2f((row[j] - m) * L2E);
            row[j] = p;
            s += p;
        }
#pragma unroll
        for (int o = 16; o; o >>= 1) s += __shfl_xor_sync(0xFFFFFFFFu, s, o);
        if (lane == 0) rinv[i] = 1.0f / (s + 1e-8f);
    }
    __syncthreads();

    // ---------------- Phase C: v = a @ X, j split across warps ----------------
    {
        const int lane = tid & 31;
        const int w    = tid >> 5;          // owns j in [w*128, w*128+128)
        const int j0   = w * (LL / 8);
        const float2* x2 = (const float2*)(x + (size_t)b * LL * DD);

        float accx[TI], accy[TI];
#pragma unroll
        for (int i = 0; i < TI; i++) { accx[i] = 0.0f; accy[i] = 0.0f; }

        for (int j = j0; j < j0 + LL / 8; j += 4) {
            float2 xv0 = x2[(j + 0) * 32 + lane];
            float2 xv1 = x2[(j + 1) * 32 + lane];
            float2 xv2 = x2[(j + 2) * 32 + lane];
            float2 xv3 = x2[(j + 3) * 32 + lane];
#pragma unroll
            for (int i = 0; i < TI; i++) {
                float4 p = *(const float4*)&et[i * EST + j];
                accx[i] = fmaf(p.x, xv0.x, accx[i]); accy[i] = fmaf(p.x, xv0.y, accy[i]);
                accx[i] = fmaf(p.y, xv1.x, accx[i]); accy[i] = fmaf(p.y, xv1.y, accy[i]);
                accx[i] = fmaf(p.z, xv2.x, accx[i]); accy[i] = fmaf(p.z, xv2.y, accy[i]);
                accx[i] = fmaf(p.w, xv3.x, accx[i]); accy[i] = fmaf(p.w, xv3.y, accy[i]);
            }
        }
        __syncthreads();   // all warps done reading et

        float* part = et;
#pragma unroll
        for (int i = 0; i < TI; i++) {
            *(float2*)&part[w * (TI * DD) + i * DD + 2 * lane] = make_float2(accx[i], accy[i]);
        }
        __syncthreads();

        const int ir = tid >> 5;
        float2 s = make_float2(0.0f, 0.0f);
#pragma unroll
        for (int ww = 0; ww < 8; ww++) {
            float2 pv = *(const float2*)&part[ww * (TI * DD) + ir * DD + 2 * lane];
            s.x += pv.x; s.y += pv.y;
        }
        const float r = rinv[ir];
        *(float2*)&out[((size_t)b * LL + i0 + ir) * DD + 2 * lane] =
            make_float2(s.x * r, s.y * r);
    }
}

// ---------------------------------------------------------------------------
extern "C" void kernel_launch(void* const* d_in, const int* in_sizes, int n_in,
                              void* d_out, int out_size) {
    const float* x   = (const float*)d_in[0];
    const float* Wt  = (const float*)d_in[1];
    const float* Wx  = (const float*)d_in[2];
    const float* Wa  = (const float*)d_in[3];
    const float* bh  = (const float*)d_in[4];
    // d_in[5] = ba : cancels under softmax -> unused
    // d_in[6] = attention_width : dead code in reference -> unused
    float* out = (float*)d_out;

    const int smem_bytes = (TI * EST + JC * KST2 + TI * UH + TI) * (int)sizeof(float);
    cudaFuncSetAttribute(attn_kernel, cudaFuncAttributeMaxDynamicSharedMemorySize, smem_bytes);

    qk_proj_kernel<<<BB * LL, 64>>>(x, Wt, Wx, bh);
    attn_kernel<<<BB * (LL / TI), 256, smem_bytes>>>(x, Wa, out);
}